// round 1
// baseline (speedup 1.0000x reference)
#include <cuda_runtime.h>

#define N_ROWS  262144
#define DIM     256
#define CLUSTER 512
#define SLACK   1024
#define NPAIRS  (CLUSTER * (CLUSTER - 1) / 2)   // 130816

// ---- device scratch (no allocations allowed) ----
__device__ int   d_cursor[CLUSTER];
__device__ int   d_perm[CLUSTER * SLACK];          // 2 MB
__device__ float d_centers[CLUSTER * DIM];         // 512 KB
__device__ float d_norms[CLUSTER];
__device__ float d_pair_sum;

// ---------------------------------------------------------------------------
// k_init: reset cursors (slack-bucket bases) and the pair-sum accumulator.
// Must run every launch (graph replays).
// ---------------------------------------------------------------------------
__global__ void k_init() {
    int t = blockIdx.x * blockDim.x + threadIdx.x;
    if (t < CLUSTER) d_cursor[t] = t * SLACK;
    if (t == 0) d_pair_sum = 0.0f;
}

// ---------------------------------------------------------------------------
// k_scatter: counting scatter of row indices into per-cluster buckets.
// 262144 int atomics over 512 counters -> issue-bound, ~1-2 us.
// ---------------------------------------------------------------------------
__global__ void __launch_bounds__(512) k_scatter(const int* __restrict__ label) {
    int r = blockIdx.x * blockDim.x + threadIdx.x;
    if (r < N_ROWS) {
        int lab = label[r];
        int pos = atomicAdd(&d_cursor[lab], 1);
        d_perm[pos] = r;
    }
}

// ---------------------------------------------------------------------------
// k_sums: one CTA per cluster. Thread t owns column t. Gather rows through
// smem-staged indices; 8 accumulators give 8 independent in-flight LDGs per
// warp iteration (MLP=8). This is the 256 MB HBM-bound pass.
// ---------------------------------------------------------------------------
__global__ void __launch_bounds__(256) k_sums(const float* __restrict__ matrix) {
    int c = blockIdx.x;
    int t = threadIdx.x;
    int cnt = d_cursor[c] - c * SLACK;
    const int* __restrict__ p = d_perm + c * SLACK;

    __shared__ int sidx[256];

    float acc[8];
#pragma unroll
    for (int u = 0; u < 8; u++) acc[u] = 0.0f;

    for (int base = 0; base < cnt; base += 256) {
        int m = min(256, cnt - base);
        __syncthreads();
        if (t < m) sidx[t] = p[base + t];
        __syncthreads();

        int r = 0;
        for (; r + 8 <= m; r += 8) {
            int idx[8];
#pragma unroll
            for (int u = 0; u < 8; u++) idx[u] = sidx[r + u];
#pragma unroll
            for (int u = 0; u < 8; u++)
                acc[u] += matrix[idx[u] * DIM + t];
        }
        for (; r < m; r++)
            acc[0] += matrix[sidx[r] * DIM + t];
    }

    float s = ((acc[0] + acc[1]) + (acc[2] + acc[3])) +
              ((acc[4] + acc[5]) + (acc[6] + acc[7]));
    float center = s / fmaxf((float)cnt, 1.0f);
    d_centers[c * DIM + t] = center;

    // block-reduce center^2 -> norms[c]
    float sq = center * center;
#pragma unroll
    for (int o = 16; o > 0; o >>= 1)
        sq += __shfl_down_sync(0xFFFFFFFFu, sq, o);

    __shared__ float wsum[8];
    if ((t & 31) == 0) wsum[t >> 5] = sq;
    __syncthreads();
    if (t < 8) {
        float v = wsum[t];
#pragma unroll
        for (int o = 4; o > 0; o >>= 1)
            v += __shfl_down_sync(0xFFu, v, o);
        if (t == 0) d_norms[c] = v;
    }
}

// ---------------------------------------------------------------------------
// k_pdist: upper-triangle 32x32 tiles of the 512x512 pair space.
// dist^2(i,j) = n_i + n_j - 2*dot(c_i, c_j); dots via register-tiled smem GEMM
// (64 threads, 4x4 micro-tile, float4 along D, D chunked 2x128).
// Row pad 132 floats (528 B stride; 528 % 128 = 16) -> conflict-free LDS.128.
// ---------------------------------------------------------------------------
__global__ void __launch_bounds__(64) k_pdist() {
    int bj = blockIdx.x, bi = blockIdx.y;
    if (bi > bj) return;

    __shared__ __align__(16) float As[32][132];
    __shared__ __align__(16) float Bs[32][132];

    int t  = threadIdx.x;      // 0..63
    int ti = t >> 3;           // 0..7
    int tj = t & 7;            // 0..7

    float acc[4][4];
#pragma unroll
    for (int i = 0; i < 4; i++)
#pragma unroll
        for (int j = 0; j < 4; j++) acc[i][j] = 0.0f;

    for (int ck = 0; ck < DIM; ck += 128) {
        __syncthreads();
        // load 32 rows x 128 floats per side; 16 float4 per thread per side
        for (int l = t; l < 32 * 32; l += 64) {
            int r = l >> 5;
            int q = (l & 31) * 4;
            *(float4*)&As[r][q] =
                *(const float4*)&d_centers[(bi * 32 + r) * DIM + ck + q];
            *(float4*)&Bs[r][q] =
                *(const float4*)&d_centers[(bj * 32 + r) * DIM + ck + q];
        }
        __syncthreads();

        for (int d = 0; d < 128; d += 4) {
            float4 a[4], b[4];
#pragma unroll
            for (int i = 0; i < 4; i++) a[i] = *(float4*)&As[ti * 4 + i][d];
#pragma unroll
            for (int j = 0; j < 4; j++) b[j] = *(float4*)&Bs[tj * 4 + j][d];
#pragma unroll
            for (int i = 0; i < 4; i++)
#pragma unroll
                for (int j = 0; j < 4; j++)
                    acc[i][j] += a[i].x * b[j].x + a[i].y * b[j].y +
                                 a[i].z * b[j].z + a[i].w * b[j].w;
        }
    }

    float local = 0.0f;
#pragma unroll
    for (int i = 0; i < 4; i++) {
        int gi = bi * 32 + ti * 4 + i;
        float ni = d_norms[gi];
#pragma unroll
        for (int j = 0; j < 4; j++) {
            int gj = bj * 32 + tj * 4 + j;
            float sq2  = ni + d_norms[gj] - 2.0f * acc[i][j];
            float dist = sqrtf(fmaxf(sq2, 1e-12f));
            if (gi < gj) local += dist;
        }
    }

    // reduce 64 threads -> one atomicAdd
#pragma unroll
    for (int o = 16; o > 0; o >>= 1)
        local += __shfl_down_sync(0xFFFFFFFFu, local, o);

    __shared__ float part[2];
    if ((t & 31) == 0) part[t >> 5] = local;
    __syncthreads();
    if (t == 0) atomicAdd(&d_pair_sum, part[0] + part[1]);
}

// ---------------------------------------------------------------------------
__global__ void k_final(float* __restrict__ out) {
    out[0] = -d_pair_sum / (float)NPAIRS;
}

// ---------------------------------------------------------------------------
extern "C" void kernel_launch(void* const* d_in, const int* in_sizes, int n_in,
                              void* d_out, int out_size) {
    const float* matrix = (const float*)d_in[0];
    const int*   label  = (const int*)d_in[1];
    float*       out    = (float*)d_out;

    k_init<<<1, 512>>>();
    k_scatter<<<N_ROWS / 512, 512>>>(label);
    k_sums<<<CLUSTER, 256>>>(matrix);
    k_pdist<<<dim3(16, 16), 64>>>();
    k_final<<<1, 1>>>(out);
}

// round 2
// speedup vs baseline: 1.2733x; 1.2733x over previous
#include <cuda_runtime.h>

#define N_ROWS  262144
#define DIM     256
#define CLUSTER 512
#define SLACK   1024
#define NPAIRS  (CLUSTER * (CLUSTER - 1) / 2)   // 130816

// ---- device scratch (no allocations allowed) ----
__device__ int   d_cursor[CLUSTER];
__device__ int   d_perm[CLUSTER * SLACK];          // 2 MB
__device__ float d_centers[CLUSTER * DIM];         // 512 KB (L2-resident)
__device__ float d_norms[CLUSTER];
__device__ float d_pair_sum;

// ---------------------------------------------------------------------------
// k_init: reset cursors (slack-bucket bases) and the pair-sum accumulator.
// ---------------------------------------------------------------------------
__global__ void k_init() {
    int t = blockIdx.x * blockDim.x + threadIdx.x;
    if (t < CLUSTER) d_cursor[t] = t * SLACK;
    if (t == 0) d_pair_sum = 0.0f;
}

// ---------------------------------------------------------------------------
// k_scatter: counting scatter of row indices into per-cluster buckets.
// ---------------------------------------------------------------------------
__global__ void __launch_bounds__(512) k_scatter(const int* __restrict__ label) {
    int r = blockIdx.x * blockDim.x + threadIdx.x;
    if (r < N_ROWS) {
        int lab = label[r];
        int pos = atomicAdd(&d_cursor[lab], 1);
        d_perm[pos] = r;
    }
}

// ---------------------------------------------------------------------------
// k_sums: one CTA per cluster. 256 threads = 64 column-groups (float4) x 4
// row-slots. Each thread keeps 8 independent LDG.128 in flight (explicit
// v[8] batch, then an add tree) -> 32 x 128B lines outstanding per warp.
// This is the 256 MB HBM-bound pass.
// ---------------------------------------------------------------------------
__global__ void __launch_bounds__(256) k_sums(const float* __restrict__ matrix) {
    int c  = blockIdx.x;
    int t  = threadIdx.x;
    int cg = t & 63;          // column group: floats cg*4 .. cg*4+3
    int s  = t >> 6;          // row slot 0..3
    int cnt = d_cursor[c] - c * SLACK;
    const int* __restrict__ p = d_perm + c * SLACK;

    __shared__ int    sidx[256];
    __shared__ float4 part[256];

    float4 acc = make_float4(0.f, 0.f, 0.f, 0.f);

    int base = 0;
    for (; base + 256 <= cnt; base += 256) {
        __syncthreads();
        sidx[t] = p[base + t];
        __syncthreads();
        // slot s handles chunk positions r*4+s (64 of them), unrolled by 8
        for (int r = 0; r < 64; r += 8) {
            float4 v[8];
#pragma unroll
            for (int u = 0; u < 8; u++) {
                int row = sidx[(r + u) * 4 + s];
                v[u] = *(const float4*)&matrix[row * DIM + cg * 4];
            }
            float4 s01, s23, s45, s67, sA, sB;
            s01.x = v[0].x + v[1].x; s01.y = v[0].y + v[1].y; s01.z = v[0].z + v[1].z; s01.w = v[0].w + v[1].w;
            s23.x = v[2].x + v[3].x; s23.y = v[2].y + v[3].y; s23.z = v[2].z + v[3].z; s23.w = v[2].w + v[3].w;
            s45.x = v[4].x + v[5].x; s45.y = v[4].y + v[5].y; s45.z = v[4].z + v[5].z; s45.w = v[4].w + v[5].w;
            s67.x = v[6].x + v[7].x; s67.y = v[6].y + v[7].y; s67.z = v[6].z + v[7].z; s67.w = v[6].w + v[7].w;
            sA.x = s01.x + s23.x; sA.y = s01.y + s23.y; sA.z = s01.z + s23.z; sA.w = s01.w + s23.w;
            sB.x = s45.x + s67.x; sB.y = s45.y + s67.y; sB.z = s45.z + s67.z; sB.w = s45.w + s67.w;
            acc.x += sA.x + sB.x; acc.y += sA.y + sB.y;
            acc.z += sA.z + sB.z; acc.w += sA.w + sB.w;
        }
    }
    // tail (< 256 remaining rows)
    {
        int m = cnt - base;
        __syncthreads();
        if (t < m) sidx[t] = p[base + t];
        __syncthreads();
        for (int r = s; r < m; r += 4) {
            int row = sidx[r];
            float4 v = *(const float4*)&matrix[row * DIM + cg * 4];
            acc.x += v.x; acc.y += v.y; acc.z += v.z; acc.w += v.w;
        }
    }

    // combine the 4 row-slots, normalize, store center + norm
    part[t] = acc;
    __syncthreads();

    float nrm = 0.0f;
    if (t < 64) {
        float4 a0 = part[t], a1 = part[t + 64], a2 = part[t + 128], a3 = part[t + 192];
        float inv = 1.0f / fmaxf((float)cnt, 1.0f);
        float4 cen;
        cen.x = (a0.x + a1.x + a2.x + a3.x) * inv;
        cen.y = (a0.y + a1.y + a2.y + a3.y) * inv;
        cen.z = (a0.z + a1.z + a2.z + a3.z) * inv;
        cen.w = (a0.w + a1.w + a2.w + a3.w) * inv;
        *(float4*)&d_centers[c * DIM + t * 4] = cen;
        nrm = cen.x * cen.x + cen.y * cen.y + cen.z * cen.z + cen.w * cen.w;
    }
#pragma unroll
    for (int o = 16; o > 0; o >>= 1)
        nrm += __shfl_down_sync(0xFFFFFFFFu, nrm, o);

    __shared__ float wsum[8];
    if ((t & 31) == 0) wsum[t >> 5] = nrm;
    __syncthreads();
    if (t == 0) d_norms[c] = wsum[0] + wsum[1];   // warps 2..7 contributed 0
}

// ---------------------------------------------------------------------------
// k_pdist: 32x32 upper-triangle tiles of the 512x512 pair space, 256 threads.
// Warp w owns j-rows w*4..w*4+3  -> smem b-loads are warp-broadcast
//                                   (conflict-free by construction).
// Lane l owns i-row l            -> a-slices streamed from global centers
//                                   (512 KB, L2-resident) into registers.
// dist^2 = n_i + n_j - 2*dot.
// ---------------------------------------------------------------------------
__global__ void __launch_bounds__(256) k_pdist() {
    int bj = blockIdx.x, bi = blockIdx.y;
    if (bi > bj) return;

    __shared__ __align__(16) float Bs[32][260];

    int t = threadIdx.x;
    int w = t >> 5;   // warp -> j group
    int l = t & 31;   // lane -> i row

    // stage B tile: rows bj*32..+31, all 256 dims (coalesced float4 loads)
    for (int x = t; x < 32 * 64; x += 256) {
        int r = x >> 6;
        int q = (x & 63) * 4;
        *(float4*)&Bs[r][q] = *(const float4*)&d_centers[(bj * 32 + r) * DIM + q];
    }
    __syncthreads();

    const float* __restrict__ arow = &d_centers[(bi * 32 + l) * DIM];

    float4 acc[4];
#pragma unroll
    for (int j = 0; j < 4; j++) acc[j] = make_float4(0.f, 0.f, 0.f, 0.f);

    for (int dc = 0; dc < DIM; dc += 32) {
        float4 a[8];
#pragma unroll
        for (int u = 0; u < 8; u++)
            a[u] = *(const float4*)&arow[dc + u * 4];
#pragma unroll
        for (int u = 0; u < 8; u++) {
#pragma unroll
            for (int j = 0; j < 4; j++) {
                float4 b = *(float4*)&Bs[w * 4 + j][dc + u * 4];
                acc[j].x += a[u].x * b.x;
                acc[j].y += a[u].y * b.y;
                acc[j].z += a[u].z * b.z;
                acc[j].w += a[u].w * b.w;
            }
        }
    }

    int gi = bi * 32 + l;
    float ni = d_norms[gi];
    float local = 0.0f;
#pragma unroll
    for (int j = 0; j < 4; j++) {
        int gj = bj * 32 + w * 4 + j;
        float dot = (acc[j].x + acc[j].y) + (acc[j].z + acc[j].w);
        float sq  = ni + d_norms[gj] - 2.0f * dot;
        if (gi < gj) local += sqrtf(fmaxf(sq, 1e-12f));
    }

    // block reduce -> one atomicAdd
#pragma unroll
    for (int o = 16; o > 0; o >>= 1)
        local += __shfl_down_sync(0xFFFFFFFFu, local, o);

    __shared__ float partw[8];
    if ((t & 31) == 0) partw[t >> 5] = local;
    __syncthreads();
    if (t == 0) {
        float sum = 0.0f;
#pragma unroll
        for (int i = 0; i < 8; i++) sum += partw[i];
        atomicAdd(&d_pair_sum, sum);
    }
}

// ---------------------------------------------------------------------------
__global__ void k_final(float* __restrict__ out) {
    out[0] = -d_pair_sum / (float)NPAIRS;
}

// ---------------------------------------------------------------------------
extern "C" void kernel_launch(void* const* d_in, const int* in_sizes, int n_in,
                              void* d_out, int out_size) {
    const float* matrix = (const float*)d_in[0];
    const int*   label  = (const int*)d_in[1];
    float*       out    = (float*)d_out;

    k_init<<<1, 512>>>();
    k_scatter<<<N_ROWS / 512, 512>>>(label);
    k_sums<<<CLUSTER, 256>>>(matrix);
    k_pdist<<<dim3(16, 16), 256>>>();
    k_final<<<1, 1>>>(out);
}

// round 3
// speedup vs baseline: 1.5118x; 1.1873x over previous
#include <cuda_runtime.h>

#define N_ROWS  262144
#define DIM     256
#define CLUSTER 512
#define SLACK   1024
#define NPAIRS  (CLUSTER * (CLUSTER - 1) / 2)   // 130816
#define NTILES  136                             // 16*17/2 upper-tri 32x32 tiles

// ---- device scratch (no allocations allowed) ----
__device__ int   d_cursor[CLUSTER];
__device__ int   d_perm[CLUSTER * SLACK];          // 2 MB
__device__ float d_centers[CLUSTER * DIM];         // 512 KB (L2-resident)
__device__ float d_norms[CLUSTER];
__device__ float d_pair_sum;

// ---------------------------------------------------------------------------
// k_init: reset cursors, norms, pair accumulator (graph replays reuse them).
// ---------------------------------------------------------------------------
__global__ void k_init() {
    int t = blockIdx.x * blockDim.x + threadIdx.x;
    if (t < CLUSTER) {
        d_cursor[t] = t * SLACK;
        d_norms[t]  = 0.0f;
    }
    if (t == 0) d_pair_sum = 0.0f;
}

// ---------------------------------------------------------------------------
// k_scatter: counting scatter of row indices into per-cluster buckets.
// ---------------------------------------------------------------------------
__global__ void __launch_bounds__(512) k_scatter(const int* __restrict__ label) {
    int r = blockIdx.x * blockDim.x + threadIdx.x;
    if (r < N_ROWS) {
        int lab = label[r];
        int pos = atomicAdd(&d_cursor[lab], 1);
        d_perm[pos] = r;
    }
}

// ---------------------------------------------------------------------------
// k_sums: 4 CTAs per cluster (64-column quarters), 128 threads =
// 16 column-groups (float4) x 8 row-slots. Each thread keeps 8 independent
// LDG.128 in flight (explicit v[8] batch + add tree) -> 4KB/warp outstanding.
// 2048 small CTAs -> ~8 CTAs/SM, negligible tail. The 256 MB HBM pass.
// ---------------------------------------------------------------------------
__global__ void __launch_bounds__(128) k_sums(const float* __restrict__ matrix) {
    int bx   = blockIdx.x;
    int c    = bx >> 2;           // cluster
    int quad = bx & 3;            // column quarter
    int t    = threadIdx.x;
    int cg   = t & 15;            // float4 group within the quarter
    int s    = t >> 4;            // row slot 0..7
    int colbase = quad * 64 + cg * 4;

    int cnt = d_cursor[c] - c * SLACK;
    const int* __restrict__ p = d_perm + c * SLACK;

    __shared__ int    sidx[256];
    __shared__ float4 part[128];

    float4 acc = make_float4(0.f, 0.f, 0.f, 0.f);

    int base = 0;
    for (; base + 256 <= cnt; base += 256) {
        __syncthreads();
        sidx[t]       = p[base + t];
        sidx[t + 128] = p[base + t + 128];
        __syncthreads();
        // slot s handles positions r*8+s (32 of them), unrolled by 8
        for (int r = 0; r < 32; r += 8) {
            float4 v[8];
#pragma unroll
            for (int u = 0; u < 8; u++) {
                int row = sidx[(r + u) * 8 + s];
                v[u] = *(const float4*)&matrix[row * DIM + colbase];
            }
            float4 s01, s23, s45, s67, sA, sB;
            s01.x = v[0].x + v[1].x; s01.y = v[0].y + v[1].y; s01.z = v[0].z + v[1].z; s01.w = v[0].w + v[1].w;
            s23.x = v[2].x + v[3].x; s23.y = v[2].y + v[3].y; s23.z = v[2].z + v[3].z; s23.w = v[2].w + v[3].w;
            s45.x = v[4].x + v[5].x; s45.y = v[4].y + v[5].y; s45.z = v[4].z + v[5].z; s45.w = v[4].w + v[5].w;
            s67.x = v[6].x + v[7].x; s67.y = v[6].y + v[7].y; s67.z = v[6].z + v[7].z; s67.w = v[6].w + v[7].w;
            sA.x = s01.x + s23.x; sA.y = s01.y + s23.y; sA.z = s01.z + s23.z; sA.w = s01.w + s23.w;
            sB.x = s45.x + s67.x; sB.y = s45.y + s67.y; sB.z = s45.z + s67.z; sB.w = s45.w + s67.w;
            acc.x += sA.x + sB.x; acc.y += sA.y + sB.y;
            acc.z += sA.z + sB.z; acc.w += sA.w + sB.w;
        }
    }
    // tail (< 256 remaining rows)
    {
        int m = cnt - base;
        __syncthreads();
        if (t < m)       sidx[t]       = p[base + t];
        if (t + 128 < m) sidx[t + 128] = p[base + t + 128];
        __syncthreads();
        for (int r = s; r < m; r += 8) {
            int row = sidx[r];
            float4 v = *(const float4*)&matrix[row * DIM + colbase];
            acc.x += v.x; acc.y += v.y; acc.z += v.z; acc.w += v.w;
        }
    }

    part[t] = acc;
    __syncthreads();

    if (t < 16) {
        float4 cen = make_float4(0.f, 0.f, 0.f, 0.f);
#pragma unroll
        for (int k = 0; k < 8; k++) {
            float4 a = part[t + k * 16];
            cen.x += a.x; cen.y += a.y; cen.z += a.z; cen.w += a.w;
        }
        float inv = 1.0f / fmaxf((float)cnt, 1.0f);
        cen.x *= inv; cen.y *= inv; cen.z *= inv; cen.w *= inv;
        *(float4*)&d_centers[c * DIM + quad * 64 + t * 4] = cen;

        float nrm = cen.x * cen.x + cen.y * cen.y + cen.z * cen.z + cen.w * cen.w;
#pragma unroll
        for (int o = 8; o > 0; o >>= 1)
            nrm += __shfl_down_sync(0xFFFFu, nrm, o);
        if (t == 0) atomicAdd(&d_norms[c], nrm);
    }
}

// ---------------------------------------------------------------------------
// k_pdist: 136 upper-triangle 32x32 tiles, 256 threads, smem both sides.
// 8 warps tile the 32x32 region as 2x4 warp-regions of 16x8 pairs; each
// thread computes a 2x2 micro-tile. Bank conflicts <= 2-way by construction.
// dist^2 = n_i + n_j - 2*dot.
// ---------------------------------------------------------------------------
__global__ void __launch_bounds__(256) k_pdist() {
    // decode upper-tri tile index -> (bi, bj), bi <= bj
    int n = blockIdx.x;
    int bi = 0;
    while (n >= 16 - bi) { n -= 16 - bi; bi++; }
    int bj = bi + n;

    __shared__ __align__(16) float As[32][132];
    __shared__ __align__(16) float Bs[32][132];

    int t = threadIdx.x;
    int l = t & 31;
    int w = t >> 5;
    int li = (w >> 2) * 16 + (l & 7) * 2;   // i rows: li, li+1
    int lj = (w & 3) * 8  + (l >> 3) * 2;   // j rows: lj, lj+1

    float4 acc00 = make_float4(0,0,0,0), acc01 = make_float4(0,0,0,0);
    float4 acc10 = make_float4(0,0,0,0), acc11 = make_float4(0,0,0,0);

    for (int ck = 0; ck < DIM; ck += 128) {
        __syncthreads();
        for (int x = t; x < 32 * 32; x += 256) {
            int r = x >> 5;
            int q = (x & 31) * 4;
            *(float4*)&As[r][q] = *(const float4*)&d_centers[(bi * 32 + r) * DIM + ck + q];
            *(float4*)&Bs[r][q] = *(const float4*)&d_centers[(bj * 32 + r) * DIM + ck + q];
        }
        __syncthreads();

#pragma unroll 4
        for (int d = 0; d < 128; d += 4) {
            float4 a0 = *(float4*)&As[li][d];
            float4 a1 = *(float4*)&As[li + 1][d];
            float4 b0 = *(float4*)&Bs[lj][d];
            float4 b1 = *(float4*)&Bs[lj + 1][d];
            acc00.x += a0.x * b0.x; acc00.y += a0.y * b0.y; acc00.z += a0.z * b0.z; acc00.w += a0.w * b0.w;
            acc01.x += a0.x * b1.x; acc01.y += a0.y * b1.y; acc01.z += a0.z * b1.z; acc01.w += a0.w * b1.w;
            acc10.x += a1.x * b0.x; acc10.y += a1.y * b0.y; acc10.z += a1.z * b0.z; acc10.w += a1.w * b0.w;
            acc11.x += a1.x * b1.x; acc11.y += a1.y * b1.y; acc11.z += a1.z * b1.z; acc11.w += a1.w * b1.w;
        }
    }

    int gi0 = bi * 32 + li;
    int gj0 = bj * 32 + lj;
    float ni0 = d_norms[gi0], ni1 = d_norms[gi0 + 1];
    float nj0 = d_norms[gj0], nj1 = d_norms[gj0 + 1];

    float local = 0.0f;
    {
        float dot = (acc00.x + acc00.y) + (acc00.z + acc00.w);
        float sq  = ni0 + nj0 - 2.0f * dot;
        if (gi0 < gj0) local += sqrtf(fmaxf(sq, 1e-12f));
    }
    {
        float dot = (acc01.x + acc01.y) + (acc01.z + acc01.w);
        float sq  = ni0 + nj1 - 2.0f * dot;
        if (gi0 < gj0 + 1) local += sqrtf(fmaxf(sq, 1e-12f));
    }
    {
        float dot = (acc10.x + acc10.y) + (acc10.z + acc10.w);
        float sq  = ni1 + nj0 - 2.0f * dot;
        if (gi0 + 1 < gj0) local += sqrtf(fmaxf(sq, 1e-12f));
    }
    {
        float dot = (acc11.x + acc11.y) + (acc11.z + acc11.w);
        float sq  = ni1 + nj1 - 2.0f * dot;
        if (gi0 + 1 < gj0 + 1) local += sqrtf(fmaxf(sq, 1e-12f));
    }

    // block reduce -> one atomicAdd
#pragma unroll
    for (int o = 16; o > 0; o >>= 1)
        local += __shfl_down_sync(0xFFFFFFFFu, local, o);

    __shared__ float partw[8];
    if ((t & 31) == 0) partw[w] = local;
    __syncthreads();
    if (t == 0) {
        float sum = 0.0f;
#pragma unroll
        for (int i = 0; i < 8; i++) sum += partw[i];
        atomicAdd(&d_pair_sum, sum);
    }
}

// ---------------------------------------------------------------------------
__global__ void k_final(float* __restrict__ out) {
    out[0] = -d_pair_sum / (float)NPAIRS;
}

// ---------------------------------------------------------------------------
extern "C" void kernel_launch(void* const* d_in, const int* in_sizes, int n_in,
                              void* d_out, int out_size) {
    const float* matrix = (const float*)d_in[0];
    const int*   label  = (const int*)d_in[1];
    float*       out    = (float*)d_out;

    k_init<<<1, 512>>>();
    k_scatter<<<N_ROWS / 512, 512>>>(label);
    k_sums<<<CLUSTER * 4, 128>>>(matrix);
    k_pdist<<<NTILES, 256>>>();
    k_final<<<1, 1>>>(out);
}